// round 2
// baseline (speedup 1.0000x reference)
#include <cuda_runtime.h>
#include <cstdint>

// ----------------------------------------------------------------------------
// L2LOptimizer: B=524288 independent elements.
//   m = 0.9*mom + g ; feats=[g,p,m]
//   relu1 = relu(W1@feats + b1)                       (64)
//   gates = relu1 @ W_eff^T + b_eff + h0 @ W_hh^T     (256)   [W_eff = W_ih@W2 folded]
//   LSTM pointwise (i,f,g,o), out = h1 @ W_out^T + b_out
//
// fp32 baseline: thread-per-element, weights broadcast from smem (130 KB),
// activations in registers. FMA-pipe bound by design (~1.0-1.3 ms predicted).
// ----------------------------------------------------------------------------

#define NW_EFF   (256 * 64)   // 16384
#define NW_HH    (256 * 64)   // 16384
#define SM_WEFF  0
#define SM_WHH   16384
#define SM_BEFF  32768        // 256
#define SM_W1    33024        // 192
#define SM_B1    33216        // 64
#define SM_WOUT  33280        // 64
#define SM_TOTAL 33344
#define SMEM_BYTES (SM_TOTAL * 4)

__device__ float g_Weff[NW_EFF];
__device__ float g_beff[256];

// ---- setup: W_eff = W_ih @ W2 ; b_eff = W_ih@b2 + b_ih + b_hh --------------
__global__ void __launch_bounds__(256)
l2l_precompute(const float* __restrict__ W_ih, const float* __restrict__ W2,
               const float* __restrict__ b2,   const float* __restrict__ b_ih,
               const float* __restrict__ b_hh)
{
    int idx = blockIdx.x * 256 + threadIdx.x;   // 0..16383
    int r = idx >> 6;
    int k = idx & 63;
    float acc = 0.f;
    #pragma unroll
    for (int t = 0; t < 64; t++)
        acc = fmaf(W_ih[r * 64 + t], W2[t * 64 + k], acc);
    g_Weff[idx] = acc;

    if (idx < 256) {
        float b = b_ih[idx] + b_hh[idx];
        #pragma unroll
        for (int t = 0; t < 64; t++)
            b = fmaf(W_ih[idx * 64 + t], b2[t], b);
        g_beff[idx] = b;
    }
}

// ---- activation helpers (fast intrinsics, ~1e-6 err: fine vs 1e-3 gate) ----
__device__ __forceinline__ float sigm(float x) {
    return __fdividef(1.0f, 1.0f + __expf(-x));
}
__device__ __forceinline__ float tanh_fast(float x) {
    // tanh(x) = 2*sigmoid(2x) - 1
    return fmaf(2.0f, __fdividef(1.0f, 1.0f + __expf(-2.0f * x)), -1.0f);
}

// ---- main kernel -----------------------------------------------------------
__global__ void __launch_bounds__(256, 1)
l2l_main(const float* __restrict__ grad, const float* __restrict__ par,
         const float* __restrict__ mom,  const float* __restrict__ h0,
         const float* __restrict__ c0,   const float* __restrict__ W_hh,
         const float* __restrict__ W1,   const float* __restrict__ b1,
         const float* __restrict__ W_out, const float* __restrict__ b_out,
         float* __restrict__ out, int B)
{
    extern __shared__ float smem[];
    const int tid = threadIdx.x;

    // cooperative weight stage (one-time, ~130 KB)
    for (int i = tid; i < SM_TOTAL; i += 256) {
        float v;
        if (i < SM_WHH)       v = g_Weff[i];
        else if (i < SM_BEFF) v = W_hh[i - SM_WHH];
        else if (i < SM_W1)   v = g_beff[i - SM_BEFF];
        else if (i < SM_B1)   v = W1[i - SM_W1];
        else if (i < SM_WOUT) v = b1[i - SM_B1];
        else                  v = W_out[i - SM_WOUT];
        smem[i] = v;
    }
    __syncthreads();

    const float* sWeff = smem + SM_WEFF;
    const float* sWhh  = smem + SM_WHH;
    const float* sbeff = smem + SM_BEFF;
    const float* sW1   = smem + SM_W1;
    const float* sb1   = smem + SM_B1;
    const float* sWout = smem + SM_WOUT;

    const int e = blockIdx.x * 256 + tid;
    if (e >= B) return;

    const float g = grad[e];
    const float p = par[e];
    const float m = fmaf(0.9f, mom[e], g);

    // relu1 = relu(W1 @ [g,p,m] + b1)
    float r1[64];
    #pragma unroll
    for (int i = 0; i < 64; i++) {
        float v = sb1[i];
        v = fmaf(sW1[i * 3 + 0], g, v);
        v = fmaf(sW1[i * 3 + 1], p, v);
        v = fmaf(sW1[i * 3 + 2], m, v);
        r1[i] = fmaxf(v, 0.0f);
    }

    // h0 row into registers (lane-divergent but one-time; L1 absorbs it)
    float h0r[64];
    {
        const float4* h0v = (const float4*)(h0 + (size_t)e * 64);
        #pragma unroll
        for (int q = 0; q < 16; q++) {
            float4 v = h0v[q];
            h0r[4 * q + 0] = v.x; h0r[4 * q + 1] = v.y;
            h0r[4 * q + 2] = v.z; h0r[4 * q + 3] = v.w;
        }
    }

    const float* c0row = c0 + (size_t)e * 64;
    const float  bo    = b_out[0];
    float upd = 0.0f;

    #pragma unroll 1
    for (int j = 0; j < 64; j++) {
        const float c0j = c0row[j];

        float ai = sbeff[j];
        float af = sbeff[j + 64];
        float ag = sbeff[j + 128];
        float ao = sbeff[j + 192];

        // relu1 contribution (W_eff rows j, j+64, j+128, j+192)
        {
            const float4* wiv = (const float4*)(sWeff + (j      ) * 64);
            const float4* wfv = (const float4*)(sWeff + (j +  64) * 64);
            const float4* wgv = (const float4*)(sWeff + (j + 128) * 64);
            const float4* wov = (const float4*)(sWeff + (j + 192) * 64);
            #pragma unroll
            for (int q = 0; q < 16; q++) {
                float4 wi = wiv[q], wf = wfv[q], wg = wgv[q], wo = wov[q];
                float x0 = r1[4 * q + 0], x1 = r1[4 * q + 1];
                float x2 = r1[4 * q + 2], x3 = r1[4 * q + 3];
                ai = fmaf(wi.x, x0, ai); ai = fmaf(wi.y, x1, ai);
                ai = fmaf(wi.z, x2, ai); ai = fmaf(wi.w, x3, ai);
                af = fmaf(wf.x, x0, af); af = fmaf(wf.y, x1, af);
                af = fmaf(wf.z, x2, af); af = fmaf(wf.w, x3, af);
                ag = fmaf(wg.x, x0, ag); ag = fmaf(wg.y, x1, ag);
                ag = fmaf(wg.z, x2, ag); ag = fmaf(wg.w, x3, ag);
                ao = fmaf(wo.x, x0, ao); ao = fmaf(wo.y, x1, ao);
                ao = fmaf(wo.z, x2, ao); ao = fmaf(wo.w, x3, ao);
            }
        }
        // h0 contribution (W_hh rows j, j+64, j+128, j+192)
        {
            const float4* wiv = (const float4*)(sWhh + (j      ) * 64);
            const float4* wfv = (const float4*)(sWhh + (j +  64) * 64);
            const float4* wgv = (const float4*)(sWhh + (j + 128) * 64);
            const float4* wov = (const float4*)(sWhh + (j + 192) * 64);
            #pragma unroll
            for (int q = 0; q < 16; q++) {
                float4 wi = wiv[q], wf = wfv[q], wg = wgv[q], wo = wov[q];
                float x0 = h0r[4 * q + 0], x1 = h0r[4 * q + 1];
                float x2 = h0r[4 * q + 2], x3 = h0r[4 * q + 3];
                ai = fmaf(wi.x, x0, ai); ai = fmaf(wi.y, x1, ai);
                ai = fmaf(wi.z, x2, ai); ai = fmaf(wi.w, x3, ai);
                af = fmaf(wf.x, x0, af); af = fmaf(wf.y, x1, af);
                af = fmaf(wf.z, x2, af); af = fmaf(wf.w, x3, af);
                ag = fmaf(wg.x, x0, ag); ag = fmaf(wg.y, x1, ag);
                ag = fmaf(wg.z, x2, ag); ag = fmaf(wg.w, x3, ag);
                ao = fmaf(wo.x, x0, ao); ao = fmaf(wo.y, x1, ao);
                ao = fmaf(wo.z, x2, ao); ao = fmaf(wo.w, x3, ao);
            }
        }

        const float is = sigm(ai);
        const float fs = sigm(af);
        const float os = sigm(ao);
        const float gt = tanh_fast(ag);
        const float c1 = fmaf(fs, c0j, is * gt);
        const float h1 = os * tanh_fast(c1);
        upd = fmaf(h1, sWout[j], upd);
    }

    out[e] = upd + bo;
}

// ---- launch ----------------------------------------------------------------
extern "C" void kernel_launch(void* const* d_in, const int* in_sizes, int n_in,
                              void* d_out, int out_size)
{
    const float* grad  = (const float*)d_in[0];
    const float* par   = (const float*)d_in[1];
    const float* mom   = (const float*)d_in[2];
    const float* h0    = (const float*)d_in[3];
    const float* c0    = (const float*)d_in[4];
    const float* W1    = (const float*)d_in[5];
    const float* b1    = (const float*)d_in[6];
    const float* W2    = (const float*)d_in[7];
    const float* b2    = (const float*)d_in[8];
    const float* W_ih  = (const float*)d_in[9];
    const float* W_hh  = (const float*)d_in[10];
    const float* b_ih  = (const float*)d_in[11];
    const float* b_hh  = (const float*)d_in[12];
    const float* W_out = (const float*)d_in[13];
    const float* b_out = (const float*)d_in[14];
    float* out = (float*)d_out;

    const int B = in_sizes[0];

    // idempotent; legal during graph capture (not a stream op, not an alloc)
    cudaFuncSetAttribute(l2l_main, cudaFuncAttributeMaxDynamicSharedMemorySize,
                         SMEM_BYTES);

    l2l_precompute<<<64, 256>>>(W_ih, W2, b2, b_ih, b_hh);

    const int nblk = (B + 255) / 256;
    l2l_main<<<nblk, 256, SMEM_BYTES>>>(grad, par, mom, h0, c0, W_hh,
                                        W1, b1, W_out, b_out, out, B);
}

// round 4
// speedup vs baseline: 4.7247x; 4.7247x over previous
#include <cuda_runtime.h>
#include <cuda_fp16.h>
#include <cstdint>

// ============================================================================
// L2LOptimizer via warp-level HMMA (mma.sync.m16n8k16) — no 'a'-gated features.
//   W_all[256,128] fp16 = [W_ih@W2 | W_hh] per gate row; K = [relu1(64)|h0(64)]
//   Per CTA (128 thr / 4 warps, 128 elements):
//     A[128,128] fp16 smem (272B-padded rows), B[256,128] fp16 smem (272B rows)
//     warp w: rows 32w..32w+31; 2 column passes of 32 gate-cols x 4 gates
//     D fragments keep (j, j+64, j+128, j+192) in-thread -> LSTM pointwise in
//     registers; W_out dot via 4-lane shfl reduce.
// ============================================================================

#define TPB 128

// padded row stride: 272 B (17 x 16B) -> conflict-free ldmatrix
#define ASTRIDE 272
#define SM_A    0
#define SM_B    (SM_A + 128 * ASTRIDE)      // 34816
#define SM_BEFF (SM_B + 256 * ASTRIDE)      // 104448
#define SM_WOUT (SM_BEFF + 256 * 4)         // 105472
#define SM_BYTES (SM_WOUT + 64 * 4)         // 105728

__device__ __half g_Wall[256 * 128];  // [gate n][k] ; k<64: W_ih@W2, k>=64: W_hh
__device__ float  g_beff[256];

// ---------------- helpers ---------------------------------------------------
__device__ __forceinline__ uint32_t smem_u32(const void* p) {
    uint32_t a;
    asm("{ .reg .u64 t; cvta.to.shared.u64 t, %1; cvt.u32.u64 %0, t; }"
        : "=r"(a) : "l"(p));
    return a;
}
__device__ __forceinline__ void ldsm_x4(uint32_t& r0, uint32_t& r1,
                                        uint32_t& r2, uint32_t& r3,
                                        uint32_t addr) {
    asm volatile("ldmatrix.sync.aligned.m8n8.x4.shared.b16 {%0,%1,%2,%3}, [%4];"
                 : "=r"(r0), "=r"(r1), "=r"(r2), "=r"(r3) : "r"(addr));
}
__device__ __forceinline__ void mma16816(float* c,
                                         uint32_t a0, uint32_t a1,
                                         uint32_t a2, uint32_t a3,
                                         uint32_t b0, uint32_t b1) {
    asm volatile(
        "mma.sync.aligned.m16n8k16.row.col.f32.f16.f16.f32 "
        "{%0,%1,%2,%3}, {%4,%5,%6,%7}, {%8,%9}, {%0,%1,%2,%3};"
        : "+f"(c[0]), "+f"(c[1]), "+f"(c[2]), "+f"(c[3])
        : "r"(a0), "r"(a1), "r"(a2), "r"(a3), "r"(b0), "r"(b1));
}

__device__ __forceinline__ float sigm(float x) {
    return __fdividef(1.0f, 1.0f + __expf(-x));
}
__device__ __forceinline__ float tanh_fast(float x) {
    return fmaf(2.0f, __fdividef(1.0f, 1.0f + __expf(-2.0f * x)), -1.0f);
}

// ---- precompute: W_all fp16 + b_eff ----------------------------------------
__global__ void __launch_bounds__(256)
l2l_precompute(const float* __restrict__ W_ih, const float* __restrict__ W2,
               const float* __restrict__ b2,   const float* __restrict__ b_ih,
               const float* __restrict__ b_hh, const float* __restrict__ W_hh)
{
    int idx = blockIdx.x * 256 + threadIdx.x;     // 0..32767
    int n = idx >> 7;
    int k = idx & 127;
    float acc;
    if (k < 64) {
        acc = 0.f;
        #pragma unroll
        for (int t = 0; t < 64; t++)
            acc = fmaf(W_ih[n * 64 + t], W2[t * 64 + k], acc);
    } else {
        acc = W_hh[n * 64 + (k - 64)];
    }
    g_Wall[idx] = __float2half_rn(acc);

    if (idx < 256) {
        float b = b_ih[idx] + b_hh[idx];
        #pragma unroll
        for (int t = 0; t < 64; t++)
            b = fmaf(W_ih[idx * 64 + t], b2[t], b);
        g_beff[idx] = b;
    }
}

// ---- main kernel -----------------------------------------------------------
__global__ void __launch_bounds__(TPB)
l2l_main(const float* __restrict__ grad, const float* __restrict__ par,
         const float* __restrict__ mom,  const float* __restrict__ h0,
         const float* __restrict__ c0,
         const float* __restrict__ W1,   const float* __restrict__ b1,
         const float* __restrict__ W_out, const float* __restrict__ b_out,
         float* __restrict__ out)
{
    extern __shared__ char smem[];
    const uint32_t sb = smem_u32(smem);
    const int tid  = threadIdx.x;
    const int lane = tid & 31;
    const int warp = tid >> 5;
    const int grpd = lane >> 2;          // 0..7
    const int tig  = lane & 3;           // 0..3
    const int e0   = blockIdx.x * TPB;

    // ---- stage B: g_Wall [256 x 128 half] -> smem rows of 272B
    {
        const uint32_t* wall = (const uint32_t*)g_Wall;
        #pragma unroll 4
        for (int idx = tid; idx < 16384; idx += TPB) {
            int n  = idx >> 6;
            int pk = idx & 63;
            *(uint32_t*)(smem + SM_B + n * ASTRIDE + pk * 4) = wall[idx];
        }
    }
    // ---- stage biases
    for (int i = tid; i < 256; i += TPB)
        ((float*)(smem + SM_BEFF))[i] = g_beff[i];
    if (tid < 64)
        ((float*)(smem + SM_WOUT))[tid] = W_out[tid];

    // ---- stage A: relu1 (k 0..63) for this thread's element
    {
        const int e = e0 + tid;
        const float g = grad[e];
        const float p = par[e];
        const float m = fmaf(0.9f, mom[e], g);
        #pragma unroll
        for (int pk = 0; pk < 32; pk++) {
            float v0 = b1[2 * pk], v1 = b1[2 * pk + 1];
            v0 = fmaf(W1[(2 * pk) * 3 + 0], g, v0);
            v0 = fmaf(W1[(2 * pk) * 3 + 1], p, v0);
            v0 = fmaf(W1[(2 * pk) * 3 + 2], m, v0);
            v1 = fmaf(W1[(2 * pk + 1) * 3 + 0], g, v1);
            v1 = fmaf(W1[(2 * pk + 1) * 3 + 1], p, v1);
            v1 = fmaf(W1[(2 * pk + 1) * 3 + 2], m, v1);
            __half2 h = __floats2half2_rn(fmaxf(v0, 0.f), fmaxf(v1, 0.f));
            *(uint32_t*)(smem + SM_A + tid * ASTRIDE + pk * 4) = *(uint32_t*)&h;
        }
    }
    // ---- stage A: h0 (k 64..127), cooperative coalesced
    {
        #pragma unroll 4
        for (int idx = tid; idx < 128 * 32; idx += TPB) {
            int row = idx >> 5;
            int pk  = idx & 31;
            float2 v = *(const float2*)(h0 + (size_t)(e0 + row) * 64 + pk * 2);
            __half2 h = __floats2half2_rn(v.x, v.y);
            *(uint32_t*)(smem + SM_A + row * ASTRIDE + 128 + pk * 4) =
                *(uint32_t*)&h;
        }
    }
    __syncthreads();

    // ---- per-lane ldmatrix base addresses
    // A tile (m16 x k16): lanes 0-7 rows m0-7 @k0 | 8-15 rows m8-15 @k0 |
    //                     16-23 rows m0-7 @k8 | 24-31 rows m8-15 @k8
    const int a_row_l = ((lane >> 3) & 1) * 8 + (lane & 7);
    const int a_koff  = ((lane >> 4) & 1) * 8;
    const uint32_t aAddr0 = sb + SM_A + (32 * warp + a_row_l) * ASTRIDE + a_koff * 2;
    const uint32_t aAddr1 = aAddr0 + 16 * ASTRIDE;
    // B tile (n16 x k16): lanes 0-7 n0-7 @k0 | 8-15 n0-7 @k8 |
    //                     16-23 n8-15 @k0 | 24-31 n8-15 @k8
    const int b_n_l  = ((lane >> 4) & 1) * 8 + (lane & 7);
    const int b_koff = ((lane >> 3) & 1) * 8;
    const uint32_t bBase = sb + SM_B + b_n_l * ASTRIDE + b_koff * 2;

    const float* sbeff = (const float*)(smem + SM_BEFF);
    const float* swout = (const float*)(smem + SM_WOUT);
    const float  bo    = b_out[0];

    float updr[2][2] = {{0.f, 0.f}, {0.f, 0.f}};   // [mtile][half]

    #pragma unroll 1
    for (int p = 0; p < 2; p++) {
        float acc[2][4][4][4];                     // [mt][gate][ntile][frag]
        #pragma unroll
        for (int mt = 0; mt < 2; mt++)
            #pragma unroll
            for (int g = 0; g < 4; g++)
                #pragma unroll
                for (int nt = 0; nt < 4; nt++)
                    #pragma unroll
                    for (int q = 0; q < 4; q++)
                        acc[mt][g][nt][q] = 0.f;

        #pragma unroll
        for (int kt = 0; kt < 8; kt++) {
            uint32_t a0[4], a1[4];
            ldsm_x4(a0[0], a0[1], a0[2], a0[3], aAddr0 + kt * 32);
            ldsm_x4(a1[0], a1[1], a1[2], a1[3], aAddr1 + kt * 32);
            #pragma unroll
            for (int g = 0; g < 4; g++) {
                #pragma unroll
                for (int tp = 0; tp < 2; tp++) {
                    const int n0 = g * 64 + p * 32 + tp * 16;
                    uint32_t b0, b1r, b2, b3;
                    ldsm_x4(b0, b1r, b2, b3, bBase + n0 * ASTRIDE + kt * 32);
                    mma16816(acc[0][g][tp * 2],     a0[0], a0[1], a0[2], a0[3], b0, b1r);
                    mma16816(acc[0][g][tp * 2 + 1], a0[0], a0[1], a0[2], a0[3], b2, b3);
                    mma16816(acc[1][g][tp * 2],     a1[0], a1[1], a1[2], a1[3], b0, b1r);
                    mma16816(acc[1][g][tp * 2 + 1], a1[0], a1[1], a1[2], a1[3], b2, b3);
                }
            }
        }

        // ---- epilogue for this pass: LSTM pointwise entirely in registers
        #pragma unroll
        for (int mt = 0; mt < 2; mt++) {
            #pragma unroll
            for (int hh = 0; hh < 2; hh++) {
                const int row = 32 * warp + 16 * mt + 8 * hh + grpd;
                const float* c0p = c0 + (size_t)(e0 + row) * 64 + p * 32 + tig * 2;
                float us = 0.f;
                #pragma unroll
                for (int nt = 0; nt < 4; nt++) {
                    const float2 cv = *(const float2*)(c0p + nt * 8);
                    #pragma unroll
                    for (int ee = 0; ee < 2; ee++) {
                        const int j = p * 32 + nt * 8 + tig * 2 + ee;
                        const int q = hh * 2 + ee;
                        const float ai = acc[mt][0][nt][q] + sbeff[j];
                        const float af = acc[mt][1][nt][q] + sbeff[j + 64];
                        const float ag = acc[mt][2][nt][q] + sbeff[j + 128];
                        const float ao = acc[mt][3][nt][q] + sbeff[j + 192];
                        const float is = sigm(ai), fs = sigm(af), os = sigm(ao);
                        const float gt = tanh_fast(ag);
                        const float c0v = (ee == 0) ? cv.x : cv.y;
                        const float c1 = fmaf(fs, c0v, is * gt);
                        const float h1 = os * tanh_fast(c1);
                        us = fmaf(h1, swout[j], us);
                    }
                }
                updr[mt][hh] += us;
            }
        }
    }

    // ---- reduce over the 4 lanes of each row group, write out
    #pragma unroll
    for (int mt = 0; mt < 2; mt++) {
        #pragma unroll
        for (int hh = 0; hh < 2; hh++) {
            float v = updr[mt][hh];
            v += __shfl_xor_sync(0xffffffffu, v, 1);
            v += __shfl_xor_sync(0xffffffffu, v, 2);
            if (tig == 0) {
                const int row = 32 * warp + 16 * mt + 8 * hh + grpd;
                out[e0 + row] = v + bo;
            }
        }
    }
}

// ---- launch ----------------------------------------------------------------
extern "C" void kernel_launch(void* const* d_in, const int* in_sizes, int n_in,
                              void* d_out, int out_size)
{
    const float* grad  = (const float*)d_in[0];
    const float* par   = (const float*)d_in[1];
    const float* mom   = (const float*)d_in[2];
    const float* h0    = (const float*)d_in[3];
    const float* c0    = (const float*)d_in[4];
    const float* W1    = (const float*)d_in[5];
    const float* b1    = (const float*)d_in[6];
    const float* W2    = (const float*)d_in[7];
    const float* b2    = (const float*)d_in[8];
    const float* W_ih  = (const float*)d_in[9];
    const float* W_hh  = (const float*)d_in[10];
    const float* b_ih  = (const float*)d_in[11];
    const float* b_hh  = (const float*)d_in[12];
    const float* W_out = (const float*)d_in[13];
    const float* b_out = (const float*)d_in[14];
    float* out = (float*)d_out;

    const int B = in_sizes[0];

    cudaFuncSetAttribute(l2l_main, cudaFuncAttributeMaxDynamicSharedMemorySize,
                         SM_BYTES);

    l2l_precompute<<<128, 256>>>(W_ih, W2, b2, b_ih, b_hh, W_hh);

    const int nblk = B / TPB;
    l2l_main<<<nblk, TPB, SM_BYTES>>>(grad, par, mom, h0, c0,
                                      W1, b1, W_out, b_out, out);
}

// round 5
// speedup vs baseline: 6.1900x; 1.3101x over previous
#include <cuda_runtime.h>
#include <cuda_fp16.h>
#include <cstdint>

// ============================================================================
// L2LOptimizer via warp-level HMMA (mma.sync.m16n8k16).
//   W_all[256,128] fp16 = [W_ih@W2 | W_hh]; K = [relu1(64) | h0(64)]
//   Per CTA (128 thr / 4 warps, 128 elements), per pass p (N-cols p*32..+31
//   of each gate): stage only the 128 active B rows -> 71 KB smem ->
//   3 CTAs/SM (12 warps). LSTM pointwise in registers with tanh.approx.
// ============================================================================

#define TPB 128

// padded row stride: 272 B (17 x 16B) -> conflict-free ldmatrix
#define ASTRIDE 272
#define SM_A    0
#define SM_B    (SM_A + 128 * ASTRIDE)      // 34816 (half of B: 128 rows)
#define SM_BEFF (SM_B + 128 * ASTRIDE)      // 69632
#define SM_WOUT (SM_BEFF + 256 * 4)         // 70656
#define SM_BYTES (SM_WOUT + 64 * 4)         // 70912

__device__ __half g_Wall[256 * 128];  // [gate n][k]; k<64: W_ih@W2, k>=64: W_hh
__device__ float  g_beff[256];

// ---------------- helpers ---------------------------------------------------
__device__ __forceinline__ uint32_t smem_u32(const void* p) {
    uint32_t a;
    asm("{ .reg .u64 t; cvta.to.shared.u64 t, %1; cvt.u32.u64 %0, t; }"
        : "=r"(a) : "l"(p));
    return a;
}
__device__ __forceinline__ void ldsm_x4(uint32_t& r0, uint32_t& r1,
                                        uint32_t& r2, uint32_t& r3,
                                        uint32_t addr) {
    asm volatile("ldmatrix.sync.aligned.m8n8.x4.shared.b16 {%0,%1,%2,%3}, [%4];"
                 : "=r"(r0), "=r"(r1), "=r"(r2), "=r"(r3) : "r"(addr));
}
__device__ __forceinline__ void mma16816(float* c,
                                         uint32_t a0, uint32_t a1,
                                         uint32_t a2, uint32_t a3,
                                         uint32_t b0, uint32_t b1) {
    asm volatile(
        "mma.sync.aligned.m16n8k16.row.col.f32.f16.f16.f32 "
        "{%0,%1,%2,%3}, {%4,%5,%6,%7}, {%8,%9}, {%0,%1,%2,%3};"
        : "+f"(c[0]), "+f"(c[1]), "+f"(c[2]), "+f"(c[3])
        : "r"(a0), "r"(a1), "r"(a2), "r"(a3), "r"(b0), "r"(b1));
}

// HW tanh (sm_75+, not 'a'-gated): 1 MUFU op.
__device__ __forceinline__ float tanha(float x) {
    float y;
    asm("tanh.approx.f32 %0, %1;" : "=f"(y) : "f"(x));
    return y;
}
__device__ __forceinline__ float sigm(float x) {
    return fmaf(0.5f, tanha(0.5f * x), 0.5f);
}

// ---- precompute: W_all fp16 + b_eff ----------------------------------------
__global__ void __launch_bounds__(256)
l2l_precompute(const float* __restrict__ W_ih, const float* __restrict__ W2,
               const float* __restrict__ b2,   const float* __restrict__ b_ih,
               const float* __restrict__ b_hh, const float* __restrict__ W_hh)
{
    int idx = blockIdx.x * 256 + threadIdx.x;     // 0..32767
    int n = idx >> 7;
    int k = idx & 127;
    float acc;
    if (k < 64) {
        acc = 0.f;
        #pragma unroll
        for (int t = 0; t < 64; t++)
            acc = fmaf(W_ih[n * 64 + t], W2[t * 64 + k], acc);
    } else {
        acc = W_hh[n * 64 + (k - 64)];
    }
    g_Wall[idx] = __float2half_rn(acc);

    if (idx < 256) {
        float b = b_ih[idx] + b_hh[idx];
        #pragma unroll
        for (int t = 0; t < 64; t++)
            b = fmaf(W_ih[idx * 64 + t], b2[t], b);
        g_beff[idx] = b;
    }
}

// ---- main kernel -----------------------------------------------------------
__global__ void __launch_bounds__(TPB, 3)
l2l_main(const float* __restrict__ grad, const float* __restrict__ par,
         const float* __restrict__ mom,  const float* __restrict__ h0,
         const float* __restrict__ c0,
         const float* __restrict__ W1,   const float* __restrict__ b1,
         const float* __restrict__ W_out, const float* __restrict__ b_out,
         float* __restrict__ out)
{
    extern __shared__ char smem[];
    const uint32_t sb = smem_u32(smem);
    const int tid  = threadIdx.x;
    const int lane = tid & 31;
    const int warp = tid >> 5;
    const int grpd = lane >> 2;          // 0..7
    const int tig  = lane & 3;           // 0..3
    const int e0   = blockIdx.x * TPB;

    const uint32_t* wall = (const uint32_t*)g_Wall;

    // ---- stage B half for pass 0: global rows g*64 + r -> local rows g*32+r
    #pragma unroll 4
    for (int idx = tid; idx < 8192; idx += TPB) {
        int lr = idx >> 6;               // 0..127
        int pk = idx & 63;
        int g  = lr >> 5;
        int r  = lr & 31;
        *(uint32_t*)(smem + SM_B + lr * ASTRIDE + pk * 4) =
            wall[(g * 64 + r) * 64 + pk];
    }
    // ---- stage biases
    for (int i = tid; i < 256; i += TPB)
        ((float*)(smem + SM_BEFF))[i] = g_beff[i];
    if (tid < 64)
        ((float*)(smem + SM_WOUT))[tid] = W_out[tid];

    // ---- stage A: relu1 (k 0..63) for this thread's element
    {
        const int e = e0 + tid;
        const float g = grad[e];
        const float p = par[e];
        const float m = fmaf(0.9f, mom[e], g);
        #pragma unroll
        for (int pk = 0; pk < 32; pk++) {
            float v0 = b1[2 * pk], v1 = b1[2 * pk + 1];
            v0 = fmaf(W1[(2 * pk) * 3 + 0], g, v0);
            v0 = fmaf(W1[(2 * pk) * 3 + 1], p, v0);
            v0 = fmaf(W1[(2 * pk) * 3 + 2], m, v0);
            v1 = fmaf(W1[(2 * pk + 1) * 3 + 0], g, v1);
            v1 = fmaf(W1[(2 * pk + 1) * 3 + 1], p, v1);
            v1 = fmaf(W1[(2 * pk + 1) * 3 + 2], m, v1);
            __half2 h = __floats2half2_rn(fmaxf(v0, 0.f), fmaxf(v1, 0.f));
            *(uint32_t*)(smem + SM_A + tid * ASTRIDE + pk * 4) = *(uint32_t*)&h;
        }
    }
    // ---- stage A: h0 (k 64..127), cooperative coalesced
    #pragma unroll 4
    for (int idx = tid; idx < 128 * 32; idx += TPB) {
        int row = idx >> 5;
        int pk  = idx & 31;
        float2 v = *(const float2*)(h0 + (size_t)(e0 + row) * 64 + pk * 2);
        __half2 h = __floats2half2_rn(v.x, v.y);
        *(uint32_t*)(smem + SM_A + row * ASTRIDE + 128 + pk * 4) =
            *(uint32_t*)&h;
    }
    __syncthreads();

    // ---- per-lane ldmatrix base addresses
    const int a_row_l = ((lane >> 3) & 1) * 8 + (lane & 7);
    const int a_koff  = ((lane >> 4) & 1) * 8;
    const uint32_t aAddr0 = sb + SM_A + (32 * warp + a_row_l) * ASTRIDE + a_koff * 2;
    const uint32_t aAddr1 = aAddr0 + 16 * ASTRIDE;
    const int b_n_l  = ((lane >> 4) & 1) * 8 + (lane & 7);
    const int b_koff = ((lane >> 3) & 1) * 8;
    const uint32_t bBase = sb + SM_B + b_n_l * ASTRIDE + b_koff * 2;

    const float* sbeff = (const float*)(smem + SM_BEFF);
    const float* swout = (const float*)(smem + SM_WOUT);
    const float  bo    = b_out[0];

    float updr[2][2] = {{0.f, 0.f}, {0.f, 0.f}};   // [mtile][half]

    #pragma unroll 1
    for (int p = 0; p < 2; p++) {
        float acc[2][4][4][4];                     // [mt][gate][ntile][frag]
        #pragma unroll
        for (int mt = 0; mt < 2; mt++)
            #pragma unroll
            for (int g = 0; g < 4; g++)
                #pragma unroll
                for (int nt = 0; nt < 4; nt++)
                    #pragma unroll
                    for (int q = 0; q < 4; q++)
                        acc[mt][g][nt][q] = 0.f;

        #pragma unroll
        for (int kt = 0; kt < 8; kt++) {
            uint32_t a0[4], a1[4];
            ldsm_x4(a0[0], a0[1], a0[2], a0[3], aAddr0 + kt * 32);
            ldsm_x4(a1[0], a1[1], a1[2], a1[3], aAddr1 + kt * 32);
            #pragma unroll
            for (int g = 0; g < 4; g++) {
                #pragma unroll
                for (int tp = 0; tp < 2; tp++) {
                    const int n0 = g * 32 + tp * 16;   // local B row
                    uint32_t b0, b1r, b2, b3;
                    ldsm_x4(b0, b1r, b2, b3, bBase + n0 * ASTRIDE + kt * 32);
                    mma16816(acc[0][g][tp * 2],     a0[0], a0[1], a0[2], a0[3], b0, b1r);
                    mma16816(acc[0][g][tp * 2 + 1], a0[0], a0[1], a0[2], a0[3], b2, b3);
                    mma16816(acc[1][g][tp * 2],     a1[0], a1[1], a1[2], a1[3], b0, b1r);
                    mma16816(acc[1][g][tp * 2 + 1], a1[0], a1[1], a1[2], a1[3], b2, b3);
                }
            }
        }

        __syncthreads();   // all warps' B ldsm for pass p complete

        // ---- restage B for pass 1 (stores drain behind the epilogue MUFUs)
        if (p == 0) {
            #pragma unroll 4
            for (int idx = tid; idx < 8192; idx += TPB) {
                int lr = idx >> 6;
                int pk = idx & 63;
                int g  = lr >> 5;
                int r  = lr & 31;
                *(uint32_t*)(smem + SM_B + lr * ASTRIDE + pk * 4) =
                    wall[(g * 64 + 32 + r) * 64 + pk];
            }
        }

        // ---- epilogue for this pass: LSTM pointwise entirely in registers
        #pragma unroll
        for (int mt = 0; mt < 2; mt++) {
            #pragma unroll
            for (int hh = 0; hh < 2; hh++) {
                const int row = 32 * warp + 16 * mt + 8 * hh + grpd;
                const float* c0p = c0 + (size_t)(e0 + row) * 64 + p * 32 + tig * 2;
                float us = 0.f;
                #pragma unroll
                for (int nt = 0; nt < 4; nt++) {
                    const float2 cv = *(const float2*)(c0p + nt * 8);
                    #pragma unroll
                    for (int ee = 0; ee < 2; ee++) {
                        const int j = p * 32 + nt * 8 + tig * 2 + ee;
                        const int q = hh * 2 + ee;
                        const float ai = acc[mt][0][nt][q] + sbeff[j];
                        const float af = acc[mt][1][nt][q] + sbeff[j + 64];
                        const float ag = acc[mt][2][nt][q] + sbeff[j + 128];
                        const float ao = acc[mt][3][nt][q] + sbeff[j + 192];
                        const float is = sigm(ai), fs = sigm(af), os = sigm(ao);
                        const float gt = tanha(ag);
                        const float c0v = (ee == 0) ? cv.x : cv.y;
                        const float c1 = fmaf(fs, c0v, is * gt);
                        const float h1 = os * tanha(c1);
                        us = fmaf(h1, swout[j], us);
                    }
                }
                updr[mt][hh] += us;
            }
        }

        if (p == 0) __syncthreads();   // B(pass1) visible before next ldsm
    }

    // ---- reduce over the 4 lanes of each row group, write out
    #pragma unroll
    for (int mt = 0; mt < 2; mt++) {
        #pragma unroll
        for (int hh = 0; hh < 2; hh++) {
            float v = updr[mt][hh];
            v += __shfl_xor_sync(0xffffffffu, v, 1);
            v += __shfl_xor_sync(0xffffffffu, v, 2);
            if (tig == 0) {
                const int row = 32 * warp + 16 * mt + 8 * hh + grpd;
                out[e0 + row] = v + bo;
            }
        }
    }
}

// ---- launch ----------------------------------------------------------------
extern "C" void kernel_launch(void* const* d_in, const int* in_sizes, int n_in,
                              void* d_out, int out_size)
{
    const float* grad  = (const float*)d_in[0];
    const float* par   = (const float*)d_in[1];
    const float* mom   = (const float*)d_in[2];
    const float* h0    = (const float*)d_in[3];
    const float* c0    = (const float*)d_in[4];
    const float* W1    = (const float*)d_in[5];
    const float* b1    = (const float*)d_in[6];
    const float* W2    = (const float*)d_in[7];
    const float* b2    = (const float*)d_in[8];
    const float* W_ih  = (const float*)d_in[9];
    const float* W_hh  = (const float*)d_in[10];
    const float* b_ih  = (const float*)d_in[11];
    const float* b_hh  = (const float*)d_in[12];
    const float* W_out = (const float*)d_in[13];
    const float* b_out = (const float*)d_in[14];
    float* out = (float*)d_out;

    const int B = in_sizes[0];

    cudaFuncSetAttribute(l2l_main, cudaFuncAttributeMaxDynamicSharedMemorySize,
                         SM_BYTES);

    l2l_precompute<<<128, 256>>>(W_ih, W2, b2, b_ih, b_hh, W_hh);

    const int nblk = B / TPB;
    l2l_main<<<nblk, TPB, SM_BYTES>>>(grad, par, mom, h0, c0,
                                      W1, b1, W_out, b_out, out);
}

// round 6
// speedup vs baseline: 7.7805x; 1.2569x over previous
#include <cuda_runtime.h>
#include <cuda_fp16.h>
#include <cstdint>

// ============================================================================
// L2LOptimizer via warp-level HMMA (mma.sync.m16n8k16).
//   W_all[256,128] fp16 = [W_ih@W2 | W_hh]; K = [relu1(64) | h0(64)]
//   B-side mma fragments are PRE-PACKED in global (g_Bfrag) in exact fragment
//   order -> one coalesced LDG.128 per (kt,g,tp), L1-resident across CTAs.
//   No B smem, no B ldmatrix. A (per-element activations) stays in smem.
//   CTA: 256 thr / 8 warps / 128 elements; warp = one m16 stripe.
//   2 N-passes of 32 gate-cols x 4 gates; LSTM pointwise in registers.
// ============================================================================

#define TPB 256

// padded row stride: 272 B (17 x 16B) -> conflict-free ldmatrix
#define ASTRIDE 272
#define SM_A    0
#define SM_BEFF (SM_A + 128 * ASTRIDE)      // 34816
#define SM_WOUT (SM_BEFF + 256 * 4)         // 35840
#define SM_BYTES (SM_WOUT + 64 * 4)         // 36096

__device__ __half g_Wall[256 * 128];  // [gate n][k]; k<64: W_ih@W2, k>=64: W_hh
__device__ float  g_beff[256];
// B fragments: index (((pass*8+kt)*4+g)*2+tp)*32 + lane -> uint4 (b0,b1,b2,b3)
__device__ uint4  g_Bfrag[4096];

// ---------------- helpers ---------------------------------------------------
__device__ __forceinline__ uint32_t smem_u32(const void* p) {
    uint32_t a;
    asm("{ .reg .u64 t; cvta.to.shared.u64 t, %1; cvt.u32.u64 %0, t; }"
        : "=r"(a) : "l"(p));
    return a;
}
__device__ __forceinline__ void ldsm_x4(uint32_t& r0, uint32_t& r1,
                                        uint32_t& r2, uint32_t& r3,
                                        uint32_t addr) {
    asm volatile("ldmatrix.sync.aligned.m8n8.x4.shared.b16 {%0,%1,%2,%3}, [%4];"
                 : "=r"(r0), "=r"(r1), "=r"(r2), "=r"(r3) : "r"(addr));
}
__device__ __forceinline__ void mma16816(float* c,
                                         uint32_t a0, uint32_t a1,
                                         uint32_t a2, uint32_t a3,
                                         uint32_t b0, uint32_t b1) {
    asm volatile(
        "mma.sync.aligned.m16n8k16.row.col.f32.f16.f16.f32 "
        "{%0,%1,%2,%3}, {%4,%5,%6,%7}, {%8,%9}, {%0,%1,%2,%3};"
        : "+f"(c[0]), "+f"(c[1]), "+f"(c[2]), "+f"(c[3])
        : "r"(a0), "r"(a1), "r"(a2), "r"(a3), "r"(b0), "r"(b1));
}
__device__ __forceinline__ float tanha(float x) {
    float y;
    asm("tanh.approx.f32 %0, %1;" : "=f"(y) : "f"(x));
    return y;
}
__device__ __forceinline__ float sigm(float x) {
    return fmaf(0.5f, tanha(0.5f * x), 0.5f);
}

// ---- precompute 1: W_all fp16 + b_eff --------------------------------------
__global__ void __launch_bounds__(256)
l2l_precompute(const float* __restrict__ W_ih, const float* __restrict__ W2,
               const float* __restrict__ b2,   const float* __restrict__ b_ih,
               const float* __restrict__ b_hh, const float* __restrict__ W_hh)
{
    int idx = blockIdx.x * 256 + threadIdx.x;     // 0..32767
    int n = idx >> 7;
    int k = idx & 127;
    float acc;
    if (k < 64) {
        acc = 0.f;
        #pragma unroll
        for (int t = 0; t < 64; t++)
            acc = fmaf(W_ih[n * 64 + t], W2[t * 64 + k], acc);
    } else {
        acc = W_hh[n * 64 + (k - 64)];
    }
    g_Wall[idx] = __float2half_rn(acc);

    if (idx < 256) {
        float b = b_ih[idx] + b_hh[idx];
        #pragma unroll
        for (int t = 0; t < 64; t++)
            b = fmaf(W_ih[idx * 64 + t], b2[t], b);
        g_beff[idx] = b;
    }
}

// ---- precompute 2: pack B fragments in mma order ---------------------------
// m16n8k16 B frag, lane l, reg r: n_local = ((r>>1)&1)*8 + (l>>2),
//                                 k_local = (r&1)*8 + (l&3)*2 (+1 for hi half)
__global__ void __launch_bounds__(256)
l2l_packB()
{
    int idx = blockIdx.x * 256 + threadIdx.x;     // 0..4095
    int lane = idx & 31;
    int t    = idx >> 5;                          // 0..127
    int tp   = t & 1;
    int g    = (t >> 1) & 3;
    int kt   = (t >> 3) & 7;
    int pass = t >> 6;

    uint32_t r[4];
    #pragma unroll
    for (int rr = 0; rr < 4; rr++) {
        int n = g * 64 + pass * 32 + tp * 16 + ((rr >> 1) & 1) * 8 + (lane >> 2);
        int k = kt * 16 + (rr & 1) * 8 + (lane & 3) * 2;
        __half2 h = __halves2half2(g_Wall[n * 128 + k], g_Wall[n * 128 + k + 1]);
        r[rr] = *(uint32_t*)&h;
    }
    g_Bfrag[idx] = make_uint4(r[0], r[1], r[2], r[3]);
}

// ---- main kernel -----------------------------------------------------------
__global__ void __launch_bounds__(TPB, 2)
l2l_main(const float* __restrict__ grad, const float* __restrict__ par,
         const float* __restrict__ mom,  const float* __restrict__ h0,
         const float* __restrict__ c0,
         const float* __restrict__ W1,   const float* __restrict__ b1,
         const float* __restrict__ W_out, const float* __restrict__ b_out,
         float* __restrict__ out)
{
    extern __shared__ char smem[];
    const uint32_t sb = smem_u32(smem);
    const int tid  = threadIdx.x;
    const int lane = tid & 31;
    const int warp = tid >> 5;           // 0..7 -> rows 16w..16w+15
    const int grpd = lane >> 2;          // 0..7
    const int tig  = lane & 3;           // 0..3
    const int e0   = blockIdx.x * 128;

    // ---- stage biases
    ((float*)(smem + SM_BEFF))[tid & 255] = g_beff[tid & 255];
    if (tid < 64)
        ((float*)(smem + SM_WOUT))[tid] = W_out[tid];

    // ---- stage A: relu1 (k 0..63); 2 threads per element (16 pairs each)
    {
        const int e_l  = tid >> 1;              // 0..127
        const int e    = e0 + e_l;
        const int pk0  = (tid & 1) * 16;
        const float g = grad[e];
        const float p = par[e];
        const float m = fmaf(0.9f, mom[e], g);
        #pragma unroll
        for (int q = 0; q < 16; q++) {
            const int pk = pk0 + q;
            float v0 = b1[2 * pk], v1 = b1[2 * pk + 1];
            v0 = fmaf(W1[(2 * pk) * 3 + 0], g, v0);
            v0 = fmaf(W1[(2 * pk) * 3 + 1], p, v0);
            v0 = fmaf(W1[(2 * pk) * 3 + 2], m, v0);
            v1 = fmaf(W1[(2 * pk + 1) * 3 + 0], g, v1);
            v1 = fmaf(W1[(2 * pk + 1) * 3 + 1], p, v1);
            v1 = fmaf(W1[(2 * pk + 1) * 3 + 2], m, v1);
            __half2 h = __floats2half2_rn(fmaxf(v0, 0.f), fmaxf(v1, 0.f));
            *(uint32_t*)(smem + SM_A + e_l * ASTRIDE + pk * 4) = *(uint32_t*)&h;
        }
    }
    // ---- stage A: h0 (k 64..127), cooperative coalesced
    #pragma unroll 4
    for (int idx = tid; idx < 128 * 32; idx += TPB) {
        int row = idx >> 5;
        int pk  = idx & 31;
        float2 v = *(const float2*)(h0 + (size_t)(e0 + row) * 64 + pk * 2);
        __half2 h = __floats2half2_rn(v.x, v.y);
        *(uint32_t*)(smem + SM_A + row * ASTRIDE + 128 + pk * 4) =
            *(uint32_t*)&h;
    }
    __syncthreads();

    // ---- A ldmatrix base address (m16 x k16 tiles)
    const uint32_t aAddr = sb + SM_A + (16 * warp + (lane & 15)) * ASTRIDE +
                           ((lane >> 4) & 1) * 16;

    const float* sbeff = (const float*)(smem + SM_BEFF);
    const float* swout = (const float*)(smem + SM_WOUT);
    const float  bo    = b_out[0];

    float updr[2] = {0.f, 0.f};          // [row half]

    #pragma unroll 1
    for (int p = 0; p < 2; p++) {
        float acc[4][4][4];              // [gate][ntile][frag]
        #pragma unroll
        for (int g = 0; g < 4; g++)
            #pragma unroll
            for (int nt = 0; nt < 4; nt++)
                #pragma unroll
                for (int q = 0; q < 4; q++)
                    acc[g][nt][q] = 0.f;

        const uint4* bf = g_Bfrag + (size_t)p * 2048 + lane;

        #pragma unroll
        for (int kt = 0; kt < 8; kt++) {
            uint32_t a0, a1, a2, a3;
            ldsm_x4(a0, a1, a2, a3, aAddr + kt * 32);
            #pragma unroll
            for (int g = 0; g < 4; g++) {
                #pragma unroll
                for (int tp = 0; tp < 2; tp++) {
                    const uint4 b = __ldg(bf + ((kt * 4 + g) * 2 + tp) * 32);
                    mma16816(acc[g][tp * 2],     a0, a1, a2, a3, b.x, b.y);
                    mma16816(acc[g][tp * 2 + 1], a0, a1, a2, a3, b.z, b.w);
                }
            }
        }

        // ---- epilogue: LSTM pointwise in registers
        #pragma unroll
        for (int hh = 0; hh < 2; hh++) {
            const int row = 16 * warp + 8 * hh + grpd;
            const float* c0p = c0 + (size_t)(e0 + row) * 64 + p * 32 + tig * 2;
            float us = 0.f;
            #pragma unroll
            for (int nt = 0; nt < 4; nt++) {
                const float2 cv = *(const float2*)(c0p + nt * 8);
                #pragma unroll
                for (int ee = 0; ee < 2; ee++) {
                    const int j = p * 32 + nt * 8 + tig * 2 + ee;
                    const int q = hh * 2 + ee;
                    const float ai = acc[0][nt][q] + sbeff[j];
                    const float af = acc[1][nt][q] + sbeff[j + 64];
                    const float ag = acc[2][nt][q] + sbeff[j + 128];
                    const float ao = acc[3][nt][q] + sbeff[j + 192];
                    const float is = sigm(ai), fs = sigm(af), os = sigm(ao);
                    const float gt = tanha(ag);
                    const float c0v = (ee == 0) ? cv.x : cv.y;
                    const float c1 = fmaf(fs, c0v, is * gt);
                    const float h1 = os * tanha(c1);
                    us = fmaf(h1, swout[j], us);
                }
            }
            updr[hh] += us;
        }
    }

    // ---- reduce over the 4 lanes of each row group, write out
    #pragma unroll
    for (int hh = 0; hh < 2; hh++) {
        float v = updr[hh];
        v += __shfl_xor_sync(0xffffffffu, v, 1);
        v += __shfl_xor_sync(0xffffffffu, v, 2);
        if (tig == 0) {
            const int row = 16 * warp + 8 * hh + grpd;
            out[e0 + row] = v + bo;
        }
    }
}

// ---- launch ----------------------------------------------------------------
extern "C" void kernel_launch(void* const* d_in, const int* in_sizes, int n_in,
                              void* d_out, int out_size)
{
    const float* grad  = (const float*)d_in[0];
    const float* par   = (const float*)d_in[1];
    const float* mom   = (const float*)d_in[2];
    const float* h0    = (const float*)d_in[3];
    const float* c0    = (const float*)d_in[4];
    const float* W1    = (const float*)d_in[5];
    const float* b1    = (const float*)d_in[6];
    const float* W2    = (const float*)d_in[7];
    const float* b2    = (const float*)d_in[8];
    const float* W_ih  = (const float*)d_in[9];
    const float* W_hh  = (const float*)d_in[10];
    const float* b_ih  = (const float*)d_in[11];
    const float* b_hh  = (const float*)d_in[12];
    const float* W_out = (const float*)d_in[13];
    const float* b_out = (const float*)d_in[14];
    float* out = (float*)d_out;

    const int B = in_sizes[0];

    cudaFuncSetAttribute(l2l_main, cudaFuncAttributeMaxDynamicSharedMemorySize,
                         SM_BYTES);

    l2l_precompute<<<128, 256>>>(W_ih, W2, b2, b_ih, b_hh, W_hh);
    l2l_packB<<<16, 256>>>();

    const int nblk = B / 128;
    l2l_main<<<nblk, TPB, SM_BYTES>>>(grad, par, mom, h0, c0,
                                      W1, b1, W_out, b_out, out);
}